// round 2
// baseline (speedup 1.0000x reference)
#include <cuda_runtime.h>
#include <cuda_bf16.h>

// db4 level-1 DWT low-pass reconstruction, register-blocked.
// x: [8192 rows, L=4096] fp32. out: low (N) then high (N).
//
//   ca[i]     = sum_{m=0..7} h[m] * X(2i+1-m)          (X = symmetric-ext x)
//   low[2k]   = h1*ca[k] + h3*ca[k+1] + h5*ca[k+2] + h7*ca[k+3]
//   low[2k+1] = h0*ca[k] + h2*ca[k+1] + h4*ca[k+2] + h6*ca[k+3]
//   high      = x - low
//
// Thread t owns outputs [16t, 16t+16): needs x[16t-6 .. 16t+21].
// Shared row is stored with halo: sxh[12 + i] = x[i], left halo reflected at
// sxh[4..11], right halo at sxh[4108..4115]. Per-thread window = 8 x LDS.128
// starting at float4 index 4t+1 (sxh+12-8 = sxh+4, 16B aligned).

#define ROW_L    4096
#define NTHREADS 256
#define HALO_L   12
#define SXH_SIZE (HALO_L + ROW_L + 12)   // 4120 floats

__global__ void __launch_bounds__(NTHREADS)
dwt_db4_kernel(const float* __restrict__ x,
               float* __restrict__ low_out,
               float* __restrict__ high_out)
{
    __shared__ float sxh[SXH_SIZE];

    const float h0 = -0.010597401784997278f;
    const float h1 =  0.032883011666982945f;
    const float h2 =  0.030841381835986965f;
    const float h3 = -0.18703481171888114f;
    const float h4 = -0.02798376941698385f;
    const float h5 =  0.6308807679295904f;
    const float h6 =  0.7148465705525415f;
    const float h7 =  0.23037781330885523f;

    const int t = threadIdx.x;
    const size_t row = blockIdx.x;
    const float* __restrict__ xr = x + row * (size_t)ROW_L;

    // Stage row into shared (float4 coalesced), interior at sxh+12 (16B aligned)
    {
        const float4* __restrict__ x4 = (const float4*)xr;
        float4* s4 = (float4*)(sxh + HALO_L);
        #pragma unroll
        for (int i = 0; i < ROW_L / 4 / NTHREADS; ++i)
            s4[t + i * NTHREADS] = x4[t + i * NTHREADS];
    }
    // Reflected halos: sxh[11 - q] = x[q]  (left),  sxh[4108 + r] = x[4095 - r]
    if (t < 8) {
        sxh[11 - t] = xr[t];
        sxh[HALO_L + ROW_L + t] = xr[ROW_L - 1 - t];
    }
    __syncthreads();

    // Load 32-float window x[16t-8 .. 16t+23] as 8 x float4 (conflict-free)
    float xv[32];
    {
        const float4* s4 = (const float4*)sxh;
        #pragma unroll
        for (int j = 0; j < 8; ++j) {
            float4 v = s4[4 * t + 1 + j];
            xv[4 * j + 0] = v.x;
            xv[4 * j + 1] = v.y;
            xv[4 * j + 2] = v.z;
            xv[4 * j + 3] = v.w;
        }
    }

    // Analysis in registers: ca[j] for global index 8t+j, j = 0..10
    // ca_j = sum_m h[m] * xv[2j + 9 - m]
    float ca[11];
    #pragma unroll
    for (int j = 0; j < 11; ++j) {
        float s;
        s = h0 * xv[2 * j + 9];
        s = fmaf(h1, xv[2 * j + 8], s);
        s = fmaf(h2, xv[2 * j + 7], s);
        s = fmaf(h3, xv[2 * j + 6], s);
        s = fmaf(h4, xv[2 * j + 5], s);
        s = fmaf(h5, xv[2 * j + 4], s);
        s = fmaf(h6, xv[2 * j + 3], s);
        s = fmaf(h7, xv[2 * j + 2], s);
        ca[j] = s;
    }

    // Synthesis + residual: 8 pairs -> 4 float4 stores per stream
    float4* __restrict__ low4  = (float4*)(low_out  + row * (size_t)ROW_L) + 4 * t;
    float4* __restrict__ high4 = (float4*)(high_out + row * (size_t)ROW_L) + 4 * t;

    #pragma unroll
    for (int g = 0; g < 4; ++g) {
        float lo[4], hi[4];
        #pragma unroll
        for (int q = 0; q < 2; ++q) {
            const int p = 2 * g + q;       // pair index within thread, 0..7
            const float c0 = ca[p], c1 = ca[p + 1], c2 = ca[p + 2], c3 = ca[p + 3];

            float le;                       // low[2k]
            le = h1 * c0;
            le = fmaf(h3, c1, le);
            le = fmaf(h5, c2, le);
            le = fmaf(h7, c3, le);

            float ld;                       // low[2k+1]
            ld = h0 * c0;
            ld = fmaf(h2, c1, ld);
            ld = fmaf(h4, c2, ld);
            ld = fmaf(h6, c3, ld);

            lo[2 * q]     = le;
            lo[2 * q + 1] = ld;
            hi[2 * q]     = xv[8 + 2 * p] - le;
            hi[2 * q + 1] = xv[9 + 2 * p] - ld;
        }
        low4[g]  = make_float4(lo[0], lo[1], lo[2], lo[3]);
        high4[g] = make_float4(hi[0], hi[1], hi[2], hi[3]);
    }
}

extern "C" void kernel_launch(void* const* d_in, const int* in_sizes, int n_in,
                              void* d_out, int out_size)
{
    const float* x = (const float*)d_in[0];
    const int n = in_sizes[0];            // 16*512*4096
    float* low  = (float*)d_out;          // outputs concatenated: (low, high)
    float* high = low + (size_t)n;
    const int rows = n / ROW_L;           // 8192
    dwt_db4_kernel<<<rows, NTHREADS>>>(x, low, high);
}

// round 4
// speedup vs baseline: 1.3631x; 1.3631x over previous
#include <cuda_runtime.h>
#include <cuda_bf16.h>

// db4 level-1 DWT low-pass reconstruction. Shuffle-based, no shared memory.
// x: [8192 rows, 4096] fp32. out = low (N floats) then high (N floats).
//
//   ca[K]     = sum_{m=0..7} h[m] * X(2K+1-m)     (X = symmetric-ext x)
//   low[2K]   = h1*ca[K] + h3*ca[K+1] + h5*ca[K+2] + h7*ca[K+3]
//   low[2K+1] = h0*ca[K] + h2*ca[K+1] + h4*ca[K+2] + h6*ca[K+3]
//   high      = x - low
//
// Thread t (256/block), group g in [0,4): owns float4 F = 256*g + t
// (outputs x[4F..4F+3]). Window w[0..15] = X(4F-6 .. 4F+9): own float4 in
// the middle, halos from lanes t-1,t-2 (shfl_up) / t+1,t+2 (shfl_down).
// Warp-edge lanes patch via symidx-clamped global loads (handles both row
// reflection and interior warp boundaries uniformly).

#define ROW_L    4096
#define NTHREADS 256

__device__ __forceinline__ int symidx(int q) {
    // symmetric pad: X(q<0) = x[-q-1]; X(q>=L) = x[2L-1-q]
    q = (q < 0) ? (-q - 1) : q;
    q = (q >= ROW_L) ? (2 * ROW_L - 1 - q) : q;
    return q;
}

__global__ void __launch_bounds__(NTHREADS)
dwt_db4_kernel(const float* __restrict__ x,
               float* __restrict__ low_out,
               float* __restrict__ high_out)
{
    const float h0 = -0.010597401784997278f;
    const float h1 =  0.032883011666982945f;
    const float h2 =  0.030841381835986965f;
    const float h3 = -0.18703481171888114f;
    const float h4 = -0.02798376941698385f;
    const float h5 =  0.6308807679295904f;
    const float h6 =  0.7148465705525415f;
    const float h7 =  0.23037781330885523f;

    const int t = threadIdx.x;
    const int l = t & 31;
    const size_t row = blockIdx.x;
    const float*  __restrict__ xr  = x + row * (size_t)ROW_L;
    const float4* __restrict__ xr4 = (const float4*)xr;
    float4* __restrict__ low4  = (float4*)(low_out  + row * (size_t)ROW_L);
    float4* __restrict__ high4 = (float4*)(high_out + row * (size_t)ROW_L);

    #pragma unroll
    for (int g = 0; g < 4; ++g) {
        const int F = g * NTHREADS + t;          // float4 index in row, 0..1023
        const float4 v = xr4[F];                 // coalesced LDG.128

        // window w[i] = X(4F - 6 + i), i = 0..15
        float w0, w1, w2, w3, w4, w5;
        float w6 = v.x, w7 = v.y, w8 = v.z, w9 = v.w;
        float w10, w11, w12, w13, w14, w15;

        // halos via shuffle (full-warp convergent)
        w2  = __shfl_up_sync(0xffffffffu, v.x, 1);
        w3  = __shfl_up_sync(0xffffffffu, v.y, 1);
        w4  = __shfl_up_sync(0xffffffffu, v.z, 1);
        w5  = __shfl_up_sync(0xffffffffu, v.w, 1);
        w0  = __shfl_up_sync(0xffffffffu, v.z, 2);
        w1  = __shfl_up_sync(0xffffffffu, v.w, 2);
        w10 = __shfl_down_sync(0xffffffffu, v.x, 1);
        w11 = __shfl_down_sync(0xffffffffu, v.y, 1);
        w12 = __shfl_down_sync(0xffffffffu, v.z, 1);
        w13 = __shfl_down_sync(0xffffffffu, v.w, 1);
        w14 = __shfl_down_sync(0xffffffffu, v.x, 2);
        w15 = __shfl_down_sync(0xffffffffu, v.y, 2);

        // warp-edge patches: symidx-clamped global loads (L2-hot lines)
        if (l == 0) {
            const int b = 4 * F - 6;
            w0 = xr[symidx(b)];     w1 = xr[symidx(b + 1)];
            w2 = xr[symidx(b + 2)]; w3 = xr[symidx(b + 3)];
            w4 = xr[symidx(b + 4)]; w5 = xr[symidx(b + 5)];
        } else if (l == 1) {
            const int b = 4 * F - 6;
            w0 = xr[symidx(b)]; w1 = xr[symidx(b + 1)];
        }
        if (l == 31) {
            const int b = 4 * F + 4;
            w10 = xr[symidx(b)];     w11 = xr[symidx(b + 1)];
            w12 = xr[symidx(b + 2)]; w13 = xr[symidx(b + 3)];
            w14 = xr[symidx(b + 4)]; w15 = xr[symidx(b + 5)];
        } else if (l == 30) {
            const int b = 4 * F + 8;
            w14 = xr[symidx(b)]; w15 = xr[symidx(b + 1)];
        }

        // analysis: ca[j] (global coeff index 2F + j), j = 0..4
        // ca_j = sum_m h[m] * w[2j + 7 - m]
        float wv[16] = { w0, w1, w2, w3, w4, w5, w6, w7,
                         w8, w9, w10, w11, w12, w13, w14, w15 };
        float ca[5];
        #pragma unroll
        for (int j = 0; j < 5; ++j) {
            float s;
            s = h0 * wv[2 * j + 7];
            s = fmaf(h1, wv[2 * j + 6], s);
            s = fmaf(h2, wv[2 * j + 5], s);
            s = fmaf(h3, wv[2 * j + 4], s);
            s = fmaf(h4, wv[2 * j + 3], s);
            s = fmaf(h5, wv[2 * j + 2], s);
            s = fmaf(h6, wv[2 * j + 1], s);
            s = fmaf(h7, wv[2 * j + 0], s);
            ca[j] = s;
        }

        // synthesis: pairs p = 0,1 -> outputs x[4F .. 4F+3]
        float le[2], lo[2];
        #pragma unroll
        for (int p = 0; p < 2; ++p) {
            float e;
            e = h1 * ca[p];
            e = fmaf(h3, ca[p + 1], e);
            e = fmaf(h5, ca[p + 2], e);
            e = fmaf(h7, ca[p + 3], e);
            le[p] = e;

            float o;
            o = h0 * ca[p];
            o = fmaf(h2, ca[p + 1], o);
            o = fmaf(h4, ca[p + 2], o);
            o = fmaf(h6, ca[p + 3], o);
            lo[p] = o;
        }

        low4[F]  = make_float4(le[0], lo[0], le[1], lo[1]);
        high4[F] = make_float4(w6 - le[0], w7 - lo[0], w8 - le[1], w9 - lo[1]);
    }
}

extern "C" void kernel_launch(void* const* d_in, const int* in_sizes, int n_in,
                              void* d_out, int out_size)
{
    const float* x = (const float*)d_in[0];
    const int n = in_sizes[0];            // 16*512*4096
    float* low  = (float*)d_out;          // outputs concatenated: (low, high)
    float* high = low + (size_t)n;
    const int rows = n / ROW_L;           // 8192
    dwt_db4_kernel<<<rows, NTHREADS>>>(x, low, high);
}

// round 5
// speedup vs baseline: 1.4517x; 1.0650x over previous
#include <cuda_runtime.h>
#include <cuda_bf16.h>

// db4 level-1 DWT low-pass reconstruction. Shuffle halos, no shared memory,
// front-batched loads (MLP=4), vectorized edge patches.
// x: [8192 rows, 4096] fp32. out = low (N floats) then high (N floats).
//
//   ca[K]     = sum_{m=0..7} h[m] * X(2K+1-m)     (X = symmetric-ext x)
//   low[2K]   = h1*ca[K] + h3*ca[K+1] + h5*ca[K+2] + h7*ca[K+3]
//   low[2K+1] = h0*ca[K] + h2*ca[K+1] + h4*ca[K+2] + h6*ca[K+3]
//   high      = x - low

#define ROW_L    4096
#define NTHREADS 256
#define NF4      (ROW_L / 4)     // 1024 float4 per row

__global__ void __launch_bounds__(NTHREADS)
dwt_db4_kernel(const float* __restrict__ x,
               float* __restrict__ low_out,
               float* __restrict__ high_out)
{
    const float h0 = -0.010597401784997278f;
    const float h1 =  0.032883011666982945f;
    const float h2 =  0.030841381835986965f;
    const float h3 = -0.18703481171888114f;
    const float h4 = -0.02798376941698385f;
    const float h5 =  0.6308807679295904f;
    const float h6 =  0.7148465705525415f;
    const float h7 =  0.23037781330885523f;

    const int t = threadIdx.x;
    const int l = t & 31;
    const size_t row = blockIdx.x;
    const float4* __restrict__ xr4 = (const float4*)(x + row * (size_t)ROW_L);
    float4* __restrict__ low4  = (float4*)(low_out  + row * (size_t)ROW_L);
    float4* __restrict__ high4 = (float4*)(high_out + row * (size_t)ROW_L);

    // Front-batched main loads: MLP = 4
    float4 vv[4];
    #pragma unroll
    for (int g = 0; g < 4; ++g)
        vv[g] = xr4[g * NTHREADS + t];

    #pragma unroll
    for (int g = 0; g < 4; ++g) {
        const int F = g * NTHREADS + t;          // float4 index in row
        const float4 v = vv[g];

        // window w[i] = X(4F - 6 + i), i = 0..15
        float w0, w1, w2, w3, w4, w5;
        float w6 = v.x, w7 = v.y, w8 = v.z, w9 = v.w;
        float w10, w11, w12, w13, w14, w15;

        // halos via shuffle (full-warp convergent)
        w2  = __shfl_up_sync(0xffffffffu, v.x, 1);
        w3  = __shfl_up_sync(0xffffffffu, v.y, 1);
        w4  = __shfl_up_sync(0xffffffffu, v.z, 1);
        w5  = __shfl_up_sync(0xffffffffu, v.w, 1);
        w0  = __shfl_up_sync(0xffffffffu, v.z, 2);
        w1  = __shfl_up_sync(0xffffffffu, v.w, 2);
        w10 = __shfl_down_sync(0xffffffffu, v.x, 1);
        w11 = __shfl_down_sync(0xffffffffu, v.y, 1);
        w12 = __shfl_down_sync(0xffffffffu, v.z, 1);
        w13 = __shfl_down_sync(0xffffffffu, v.w, 1);
        w14 = __shfl_down_sync(0xffffffffu, v.x, 2);
        w15 = __shfl_down_sync(0xffffffffu, v.y, 2);

        // warp-edge patches: vectorized predicated loads (L2-hot), with
        // explicit swizzle for the (rare) row-end reflected cases.
        if (l == 0) {
            // need x[4F-6 .. 4F-1]
            const bool refl = (F == 0);
            const float4 A = xr4[refl ? 1 : F - 2];
            const float4 B = xr4[refl ? 0 : F - 1];
            if (refl) { w0 = A.y; w1 = A.x; w2 = B.w; w3 = B.z; w4 = B.y; w5 = B.x; }
            else      { w0 = A.z; w1 = A.w; w2 = B.x; w3 = B.y; w4 = B.z; w5 = B.w; }
        } else if (l == 1) {
            // need x[4F-6], x[4F-5]
            const bool refl = (F == 1);
            const float4 A = xr4[refl ? 0 : F - 2];
            if (refl) { w0 = A.y; w1 = A.x; }
            else      { w0 = A.z; w1 = A.w; }
        }
        if (l == 31) {
            // need x[4F+4 .. 4F+9]
            const bool refl = (F == NF4 - 1);
            const float4 C = xr4[refl ? (NF4 - 1) : F + 1];
            const float4 D = xr4[refl ? (NF4 - 2) : F + 2];
            if (refl) { w10 = C.w; w11 = C.z; w12 = C.y; w13 = C.x; w14 = D.w; w15 = D.z; }
            else      { w10 = C.x; w11 = C.y; w12 = C.z; w13 = C.w; w14 = D.x; w15 = D.y; }
        } else if (l == 30) {
            // need x[4F+8], x[4F+9]
            const bool refl = (F == NF4 - 2);
            const float4 D = xr4[refl ? (NF4 - 1) : F + 2];
            if (refl) { w14 = D.w; w15 = D.z; }
            else      { w14 = D.x; w15 = D.y; }
        }

        // analysis: ca[j] (global coeff index 2F + j), j = 0..4
        // ca_j = sum_m h[m] * w[2j + 7 - m]
        float wv[16] = { w0, w1, w2, w3, w4, w5, w6, w7,
                         w8, w9, w10, w11, w12, w13, w14, w15 };
        float ca[5];
        #pragma unroll
        for (int j = 0; j < 5; ++j) {
            float s;
            s = h0 * wv[2 * j + 7];
            s = fmaf(h1, wv[2 * j + 6], s);
            s = fmaf(h2, wv[2 * j + 5], s);
            s = fmaf(h3, wv[2 * j + 4], s);
            s = fmaf(h4, wv[2 * j + 3], s);
            s = fmaf(h5, wv[2 * j + 2], s);
            s = fmaf(h6, wv[2 * j + 1], s);
            s = fmaf(h7, wv[2 * j + 0], s);
            ca[j] = s;
        }

        // synthesis: pairs p = 0,1 -> outputs x[4F .. 4F+3]
        float le[2], lo[2];
        #pragma unroll
        for (int p = 0; p < 2; ++p) {
            float e;
            e = h1 * ca[p];
            e = fmaf(h3, ca[p + 1], e);
            e = fmaf(h5, ca[p + 2], e);
            e = fmaf(h7, ca[p + 3], e);
            le[p] = e;

            float o;
            o = h0 * ca[p];
            o = fmaf(h2, ca[p + 1], o);
            o = fmaf(h4, ca[p + 2], o);
            o = fmaf(h6, ca[p + 3], o);
            lo[p] = o;
        }

        low4[F]  = make_float4(le[0], lo[0], le[1], lo[1]);
        high4[F] = make_float4(w6 - le[0], w7 - lo[0], w8 - le[1], w9 - lo[1]);
    }
}

extern "C" void kernel_launch(void* const* d_in, const int* in_sizes, int n_in,
                              void* d_out, int out_size)
{
    const float* x = (const float*)d_in[0];
    const int n = in_sizes[0];            // 16*512*4096
    float* low  = (float*)d_out;          // outputs concatenated: (low, high)
    float* high = low + (size_t)n;
    const int rows = n / ROW_L;           // 8192
    dwt_db4_kernel<<<rows, NTHREADS>>>(x, low, high);
}